// round 1
// baseline (speedup 1.0000x reference)
#include <cuda_runtime.h>
#include <math.h>

// Problem constants
#define B_  32
#define P_  1024
#define N_  1024
#define E_  128
#define HQ_ 128
#define SQRT_E_F 11.313708498984761f

// GEMM tiling
#define BMT 128
#define BNT 128
#define BKT 8
#define SPAD 132   // padded smem row (conflict-free transposed stores, 16B-aligned rows)

// ---------------- scratch (device globals; no allocations allowed) ----------------
__device__ float g_ekv[(size_t)B_ * N_ * 256];   // [b][n][0:128]=ek, [128:256]=ek*v
__device__ float g_sq [(size_t)B_ * P_ * HQ_];   // sigmoid(q)
__device__ float g_nd [(size_t)B_ * P_ * 256];   // [0:128]=den, [128:256]=num
__device__ float g_aft[(size_t)B_ * P_ * HQ_];   // AFT_out
__device__ float g_rowsum[B_ * P_];              // softmax denominators

// ---------------- shared inner product: 8x8 micro-tile per thread ----------------
__device__ __forceinline__ void mm_inner(float acc[8][8],
                                         const float (*As)[SPAD],
                                         const float (*Bs)[SPAD],
                                         int tx, int ty) {
#pragma unroll
    for (int kk = 0; kk < BKT; kk++) {
        float a[8], bb[8];
        *(float4*)&a[0]  = *(const float4*)&As[kk][ty * 8];
        *(float4*)&a[4]  = *(const float4*)&As[kk][ty * 8 + 4];
        *(float4*)&bb[0] = *(const float4*)&Bs[kk][tx * 8];
        *(float4*)&bb[4] = *(const float4*)&Bs[kk][tx * 8 + 4];
#pragma unroll
        for (int i = 0; i < 8; i++)
#pragma unroll
            for (int j = 0; j < 8; j++)
                acc[i][j] = fmaf(a[i], bb[j], acc[i][j]);
    }
}

// ---------------- utility ----------------
__global__ void zero_rowsum_k() {
    int i = blockIdx.x * blockDim.x + threadIdx.x;
    if (i < B_ * P_) g_rowsum[i] = 0.f;
}

// ---------------- K1: k = enc@Wk, v = enc@Wv (raw), per 128x128 tile ----------------
__global__ __launch_bounds__(256) void k1_kv_gemm(const float* __restrict__ enc,
                                                  const float* __restrict__ Wk,
                                                  const float* __restrict__ Wv) {
    __shared__ float As[BKT][SPAD];
    __shared__ float Bs[BKT][SPAD];
    int b = blockIdx.z, mt = blockIdx.y, ct = blockIdx.x;
    const float* A = enc + ((size_t)b * N_ + (size_t)mt * BMT) * E_;
    const float* W = ct ? Wv : Wk;
    float* C = g_ekv + ((size_t)b * N_ + (size_t)mt * BMT) * 256 + ct * 128;
    int tid = threadIdx.x, tx = tid & 15, ty = tid >> 4;
    float acc[8][8] = {};
    for (int kt = 0; kt < E_; kt += BKT) {
        {
            int r = tid >> 1, cc = (tid & 1) * 4;
            float4 v = *(const float4*)(A + (size_t)r * E_ + kt + cc);
            As[cc][r] = v.x; As[cc + 1][r] = v.y; As[cc + 2][r] = v.z; As[cc + 3][r] = v.w;
        }
#pragma unroll
        for (int i = 0; i < 4; i++) {
            int idx = tid + i * 256;
            int r = idx >> 7, cc = idx & 127;
            Bs[r][cc] = W[(size_t)(kt + r) * HQ_ + cc];
        }
        __syncthreads();
        mm_inner(acc, As, Bs, tx, ty);
        __syncthreads();
    }
#pragma unroll
    for (int i = 0; i < 8; i++)
#pragma unroll
        for (int j = 0; j < 8; j++)
            C[(size_t)(ty * 8 + i) * 256 + tx * 8 + j] = acc[i][j];
}

// ---------------- K1b: in-place ek = exp(k), ekv = ek*v ----------------
__global__ void k1b_expkv() {
    size_t i = (size_t)blockIdx.x * blockDim.x + threadIdx.x;  // over B*N*128
    size_t bn = i >> 7; int d = (int)(i & 127);
    float k = g_ekv[bn * 256 + d];
    float v = g_ekv[bn * 256 + 128 + d];
    float ek = expf(k);
    g_ekv[bn * 256 + d]       = ek;
    g_ekv[bn * 256 + 128 + d] = ek * v;
}

// ---------------- K2: q = q1@Wq1 + q2@Wq2 + last@Wql[:128] (+rank-2) -> sigmoid ----------------
__global__ __launch_bounds__(256) void k2_q_gemm(const float* __restrict__ q1,
                                                 const float* __restrict__ q2,
                                                 const float* __restrict__ qlast,
                                                 const float* __restrict__ Wq1,
                                                 const float* __restrict__ Wq2,
                                                 const float* __restrict__ Wql,
                                                 const float* __restrict__ loadv,
                                                 const float* __restrict__ leftv) {
    __shared__ float As[BKT][SPAD];
    __shared__ float Bs[BKT][SPAD];
    int b = blockIdx.z, mt = blockIdx.y;
    size_t aoff = ((size_t)b * P_ + (size_t)mt * BMT) * E_;
    const float* Aseg[3] = { q1 + aoff, q2 + aoff, qlast + aoff };
    const float* Bseg[3] = { Wq1, Wq2, Wql };
    int tid = threadIdx.x, tx = tid & 15, ty = tid >> 4;
    float acc[8][8] = {};
    for (int kt = 0; kt < 384; kt += BKT) {
        int seg = kt >> 7, kl = kt & 127;
        const float* A = Aseg[seg];
        const float* W = Bseg[seg];
        {
            int r = tid >> 1, cc = (tid & 1) * 4;
            float4 v = *(const float4*)(A + (size_t)r * E_ + kl + cc);
            As[cc][r] = v.x; As[cc + 1][r] = v.y; As[cc + 2][r] = v.z; As[cc + 3][r] = v.w;
        }
#pragma unroll
        for (int i = 0; i < 4; i++) {
            int idx = tid + i * 256;
            int r = idx >> 7, cc = idx & 127;
            Bs[r][cc] = W[(size_t)(kl + r) * HQ_ + cc];
        }
        __syncthreads();
        mm_inner(acc, As, Bs, tx, ty);
        __syncthreads();
    }
#pragma unroll
    for (int i = 0; i < 8; i++) {
        int p = mt * BMT + ty * 8 + i;
        float ld = loadv[b * P_ + p];
        float lf = leftv[b * P_ + p];
#pragma unroll
        for (int j = 0; j < 8; j++) {
            int d = tx * 8 + j;
            float q = acc[i][j] + ld * Wql[128 * HQ_ + d] + lf * Wql[129 * HQ_ + d];
            g_sq[((size_t)b * P_ + p) * HQ_ + d] = 1.f / (1.f + __expf(-q));
        }
    }
}

// ---------------- K3: [den|num] = exp(ninf - c*cur_dist) @ [ek|ekv]  (the big GEMM) ----------------
__global__ __launch_bounds__(256) void k3_aft_gemm(const float* __restrict__ cur,
                                                   const float* __restrict__ ninf,
                                                   const float* __restrict__ lsp,
                                                   const float* __restrict__ alp) {
    __shared__ float As[BKT][SPAD];
    __shared__ float Bs[BKT][SPAD];
    int b = blockIdx.z, mt = blockIdx.y, ct = blockIdx.x;
    const float* A  = cur  + ((size_t)b * P_ + (size_t)mt * BMT) * N_;
    const float* Nf = ninf + ((size_t)b * P_ + (size_t)mt * BMT) * N_;
    const float* Bg = g_ekv + (size_t)b * N_ * 256 + ct * 128;
    float* C = g_nd + ((size_t)b * P_ + (size_t)mt * BMT) * 256 + ct * 128;
    float cmul = lsp[0] * alp[0];
    int tid = threadIdx.x, tx = tid & 15, ty = tid >> 4;
    float acc[8][8] = {};
    for (int kt = 0; kt < N_; kt += BKT) {
        {
            int r = tid >> 1, cc = (tid & 1) * 4;
            float4 x = *(const float4*)(A  + (size_t)r * N_ + kt + cc);
            float4 m = *(const float4*)(Nf + (size_t)r * N_ + kt + cc);
            As[cc][r]     = __expf(m.x - cmul * x.x);
            As[cc + 1][r] = __expf(m.y - cmul * x.y);
            As[cc + 2][r] = __expf(m.z - cmul * x.z);
            As[cc + 3][r] = __expf(m.w - cmul * x.w);
        }
#pragma unroll
        for (int i = 0; i < 4; i++) {
            int idx = tid + i * 256;
            int r = idx >> 7, cc = idx & 127;
            Bs[r][cc] = Bg[(size_t)(kt + r) * 256 + cc];
        }
        __syncthreads();
        mm_inner(acc, As, Bs, tx, ty);
        __syncthreads();
    }
#pragma unroll
    for (int i = 0; i < 8; i++)
#pragma unroll
        for (int j = 0; j < 8; j++)
            C[(size_t)(ty * 8 + i) * 256 + tx * 8 + j] = acc[i][j];
}

// ---------------- K3b: AFT_out = sigmoid_q * num / (den + 1e-20) ----------------
__global__ void k3b_aft() {
    size_t i = (size_t)blockIdx.x * blockDim.x + threadIdx.x;  // over B*P*128
    size_t bp = i >> 7; int d = (int)(i & 127);
    float den = g_nd[bp * 256 + d];
    float num = g_nd[bp * 256 + 128 + d];
    g_aft[i] = g_sq[i] * num / (den + 1e-20f);
}

// ---------------- K4: score GEMM + tanh-clip + exp + per-row partial sums ----------------
__global__ __launch_bounds__(256) void k4_score_gemm(const float* __restrict__ enc,
                                                     const float* __restrict__ cur,
                                                     const float* __restrict__ ninf,
                                                     const float* __restrict__ lsp,
                                                     const float* __restrict__ palp,
                                                     float* __restrict__ out) {
    __shared__ float As[BKT][SPAD];
    __shared__ float Bs[BKT][SPAD];
    __shared__ float rs[BMT];
    int b = blockIdx.z, mt = blockIdx.y, nt = blockIdx.x;
    const float* A  = g_aft + ((size_t)b * P_ + (size_t)mt * BMT) * HQ_;
    const float* Bn = enc   + ((size_t)b * N_ + (size_t)nt * BNT) * E_;
    float pc = lsp[0] * palp[0];
    int tid = threadIdx.x, tx = tid & 15, ty = tid >> 4;
    if (tid < BMT) rs[tid] = 0.f;
    float acc[8][8] = {};
    for (int kt = 0; kt < E_; kt += BKT) {
        {
            int r = tid >> 1, cc = (tid & 1) * 4;
            float4 v = *(const float4*)(A + (size_t)r * HQ_ + kt + cc);
            As[cc][r] = v.x; As[cc + 1][r] = v.y; As[cc + 2][r] = v.z; As[cc + 3][r] = v.w;
        }
        // B: transpose load  Bs[d][n] = enc[(nt*128+n)*128 + kt + d]
#pragma unroll
        for (int i = 0; i < 4; i++) {
            int idx = tid + i * 256;
            int d = idx & 7, n = idx >> 3;
            Bs[d][n] = Bn[(size_t)n * E_ + kt + d];
        }
        __syncthreads();
        mm_inner(acc, As, Bs, tx, ty);
        __syncthreads();
    }
    size_t base = (size_t)b * P_ * N_;
#pragma unroll
    for (int i = 0; i < 8; i++) {
        int p = mt * BMT + ty * 8 + i;
        float rsum = 0.f;
#pragma unroll
        for (int j = 0; j < 8; j++) {
            int n = nt * BNT + tx * 8 + j;
            size_t idx = base + (size_t)p * N_ + n;
            float s = acc[i][j] * (1.0f / SQRT_E_F) - pc * cur[idx];
            float u = __expf(10.0f * tanhf(s) + ninf[idx]);   // clip<=10 => no max-sub needed
            out[idx] = u;
            rsum += u;
        }
        atomicAdd(&rs[ty * 8 + i], rsum);
    }
    __syncthreads();
    if (tid < BMT) atomicAdd(&g_rowsum[b * P_ + mt * BMT + tid], rs[tid]);
}

// ---------------- K4b: normalize ----------------
__global__ void k4b_norm(float* __restrict__ out) {
    size_t i4 = ((size_t)blockIdx.x * blockDim.x + threadIdx.x) * 4;  // over B*P*N
    size_t row = i4 >> 10;  // N_=1024
    float inv = 1.0f / g_rowsum[row];
    float4 v = *(float4*)(out + i4);
    v.x *= inv; v.y *= inv; v.z *= inv; v.w *= inv;
    *(float4*)(out + i4) = v;
}

// ---------------- launch ----------------
extern "C" void kernel_launch(void* const* d_in, const int* in_sizes, int n_in,
                              void* d_out, int out_size) {
    const float* enc   = (const float*)d_in[0];
    const float* q1    = (const float*)d_in[1];
    const float* q2    = (const float*)d_in[2];
    const float* qlast = (const float*)d_in[3];
    const float* loadv = (const float*)d_in[4];
    const float* leftv = (const float*)d_in[5];
    const float* cur   = (const float*)d_in[6];
    const float* lsp   = (const float*)d_in[7];
    const float* ninf  = (const float*)d_in[8];
    const float* Wq1   = (const float*)d_in[9];
    const float* Wq2   = (const float*)d_in[10];
    const float* Wql   = (const float*)d_in[11];
    const float* Wk    = (const float*)d_in[12];
    const float* Wv    = (const float*)d_in[13];
    const float* aalp  = (const float*)d_in[14];
    const float* palp  = (const float*)d_in[15];
    float* out = (float*)d_out;

    zero_rowsum_k<<<(B_ * P_ + 255) / 256, 256>>>();
    k1_kv_gemm<<<dim3(2, N_ / BMT, B_), 256>>>(enc, Wk, Wv);
    k1b_expkv<<<(B_ * N_ * 128) / 256, 256>>>();
    k2_q_gemm<<<dim3(1, P_ / BMT, B_), 256>>>(q1, q2, qlast, Wq1, Wq2, Wql, loadv, leftv);
    k3_aft_gemm<<<dim3(2, P_ / BMT, B_), 256>>>(cur, ninf, lsp, aalp);
    k3b_aft<<<(B_ * P_ * 128) / 256, 256>>>();
    k4_score_gemm<<<dim3(N_ / BNT, P_ / BMT, B_), 256>>>(enc, cur, ninf, lsp, palp, out);
    k4b_norm<<<(B_ * (size_t)P_ * N_ / 4) / 256, 256>>>(out);
}

// round 3
// speedup vs baseline: 1.4358x; 1.4358x over previous
#include <cuda_runtime.h>
#include <math.h>

#define B_  32
#define P_  1024
#define N_  1024
#define E_  128
#define HQ_ 128
#define SQRT_E_F 11.313708498984761f

// tensor-core tiling
#define BM 128
#define BN 128
#define BK 16
#define SPW 132   // padded smem row

// ---------------- scratch ----------------
__device__ float g_ekv[(size_t)B_ * N_ * 256];   // [b][n][0:128]=ek, [128:256]=ek*v
__device__ float g_sq [(size_t)B_ * P_ * HQ_];   // sigmoid(q)
__device__ float g_nd [(size_t)B_ * P_ * 256];   // [0:128]=den, [128:256]=num
__device__ float g_aft[(size_t)B_ * P_ * HQ_];   // AFT_out
__device__ float g_rowsum[B_ * P_];

// ---------------- tf32 helpers ----------------
__device__ __forceinline__ unsigned f2tf(float x) {
    unsigned r; asm("cvt.rna.tf32.f32 %0, %1;" : "=r"(r) : "f"(x)); return r;
}

__device__ __forceinline__ void mma8(float* d, const unsigned* a, const unsigned* b) {
    asm("mma.sync.aligned.m16n8k8.row.col.f32.tf32.tf32.f32 "
        "{%0,%1,%2,%3},{%4,%5,%6,%7},{%8,%9},{%0,%1,%2,%3};"
        : "+f"(d[0]), "+f"(d[1]), "+f"(d[2]), "+f"(d[3])
        : "r"(a[0]), "r"(a[1]), "r"(a[2]), "r"(a[3]), "r"(b[0]), "r"(b[1]));
}

// warp computes 64x32 out of the 128x128 block tile; tf32x3 for fp32 accuracy
__device__ __forceinline__ void wtile(float acc[4][4][4],
                                      const float (*As)[SPW], const float (*Bs)[SPW],
                                      int wm0, int wn0, int lane) {
    const int gk = lane & 3, gr = lane >> 2;
#pragma unroll
    for (int ks = 0; ks < BK; ks += 8) {
        unsigned bh[4][2], bl[4][2];
#pragma unroll
        for (int u = 0; u < 4; u++) {
            float b0 = Bs[ks + gk    ][wn0 + u * 8 + gr];
            float b1 = Bs[ks + gk + 4][wn0 + u * 8 + gr];
            bh[u][0] = f2tf(b0); bl[u][0] = f2tf(b0 - __uint_as_float(bh[u][0]));
            bh[u][1] = f2tf(b1); bl[u][1] = f2tf(b1 - __uint_as_float(bh[u][1]));
        }
#pragma unroll
        for (int t = 0; t < 4; t++) {
            float a0 = As[ks + gk    ][wm0 + t * 16 + gr];
            float a1 = As[ks + gk    ][wm0 + t * 16 + gr + 8];
            float a2 = As[ks + gk + 4][wm0 + t * 16 + gr];
            float a3 = As[ks + gk + 4][wm0 + t * 16 + gr + 8];
            unsigned ah[4] = { f2tf(a0), f2tf(a1), f2tf(a2), f2tf(a3) };
            unsigned al[4] = { f2tf(a0 - __uint_as_float(ah[0])),
                               f2tf(a1 - __uint_as_float(ah[1])),
                               f2tf(a2 - __uint_as_float(ah[2])),
                               f2tf(a3 - __uint_as_float(ah[3])) };
#pragma unroll
            for (int u = 0; u < 4; u++) {
                mma8(acc[t][u], ah, bh[u]);
                mma8(acc[t][u], al, bh[u]);
                mma8(acc[t][u], ah, bl[u]);
            }
        }
    }
}

// ---------------- utility ----------------
__global__ void zero_rowsum_k() {
    int i = blockIdx.x * blockDim.x + threadIdx.x;
    if (i < B_ * P_) g_rowsum[i] = 0.f;
}

// ---------------- K1: k = enc@Wk, v = enc@Wv ----------------
__global__ __launch_bounds__(256) void k1_kv(const float* __restrict__ enc,
                                             const float* __restrict__ Wk,
                                             const float* __restrict__ Wv) {
    __shared__ float As[2][BK][SPW], Bs[2][BK][SPW];
    int b = blockIdx.z, mt = blockIdx.y, ct = blockIdx.x;
    const float* A = enc + ((size_t)b * N_ + (size_t)mt * BM) * E_;
    const float* W = ct ? Wv : Wk;
    float* C = g_ekv + ((size_t)b * N_ + (size_t)mt * BM) * 256 + ct * 128;
    int tid = threadIdx.x, lane = tid & 31, wid = tid >> 5;
    int wm0 = (wid >> 2) * 64, wn0 = (wid & 3) * 32;
    float acc[4][4][4] = {};
#pragma unroll
    for (int i = 0; i < 2; i++) {
        int idx = tid + i * 256;
        int m = idx >> 2, c4 = (idx & 3) * 4;
        float4 v = *(const float4*)(A + (size_t)m * E_ + c4);
        As[0][c4][m] = v.x; As[0][c4 + 1][m] = v.y; As[0][c4 + 2][m] = v.z; As[0][c4 + 3][m] = v.w;
        int k = idx >> 5, n4 = (idx & 31) * 4;
        *(float4*)&Bs[0][k][n4] = *(const float4*)(W + (size_t)k * HQ_ + n4);
    }
    __syncthreads();
    int buf = 0;
    for (int kt = 0; kt < E_; kt += BK) {
        float4 pa[2], pb[2];
        bool nx = (kt + BK) < E_;
        if (nx) {
#pragma unroll
            for (int i = 0; i < 2; i++) {
                int idx = tid + i * 256;
                int m = idx >> 2, c4 = (idx & 3) * 4;
                pa[i] = *(const float4*)(A + (size_t)m * E_ + kt + BK + c4);
                int k = idx >> 5, n4 = (idx & 31) * 4;
                pb[i] = *(const float4*)(W + (size_t)(kt + BK + k) * HQ_ + n4);
            }
        }
        wtile(acc, As[buf], Bs[buf], wm0, wn0, lane);
        if (nx) {
#pragma unroll
            for (int i = 0; i < 2; i++) {
                int idx = tid + i * 256;
                int m = idx >> 2, c4 = (idx & 3) * 4;
                As[buf ^ 1][c4][m] = pa[i].x; As[buf ^ 1][c4 + 1][m] = pa[i].y;
                As[buf ^ 1][c4 + 2][m] = pa[i].z; As[buf ^ 1][c4 + 3][m] = pa[i].w;
                int k = idx >> 5, n4 = (idx & 31) * 4;
                *(float4*)&Bs[buf ^ 1][k][n4] = pb[i];
            }
        }
        __syncthreads();
        buf ^= 1;
    }
    int gr = lane >> 2, gc = (lane & 3) * 2;
#pragma unroll
    for (int t = 0; t < 4; t++)
#pragma unroll
        for (int u = 0; u < 4; u++) {
            int r = wm0 + t * 16 + gr, c = wn0 + u * 8 + gc;
            *(float2*)&C[(size_t)r * 256 + c]       = make_float2(acc[t][u][0], acc[t][u][1]);
            *(float2*)&C[(size_t)(r + 8) * 256 + c] = make_float2(acc[t][u][2], acc[t][u][3]);
        }
}

// ---------------- K1b: ek = exp(k), ekv = ek*v ----------------
__global__ void k1b_expkv() {
    size_t i = (size_t)blockIdx.x * blockDim.x + threadIdx.x;
    size_t bn = i >> 7; int d = (int)(i & 127);
    float k = g_ekv[bn * 256 + d];
    float v = g_ekv[bn * 256 + 128 + d];
    float ek = __expf(k);
    g_ekv[bn * 256 + d]       = ek;
    g_ekv[bn * 256 + 128 + d] = ek * v;
}

// ---------------- K2: q projections + sigmoid ----------------
__global__ __launch_bounds__(256) void k2_q(const float* __restrict__ q1,
                                            const float* __restrict__ q2,
                                            const float* __restrict__ qlast,
                                            const float* __restrict__ Wq1,
                                            const float* __restrict__ Wq2,
                                            const float* __restrict__ Wql,
                                            const float* __restrict__ loadv,
                                            const float* __restrict__ leftv) {
    __shared__ float As[2][BK][SPW], Bs[2][BK][SPW];
    int b = blockIdx.z, mt = blockIdx.y;
    size_t aoff = ((size_t)b * P_ + (size_t)mt * BM) * E_;
    const float* Aseg[3] = { q1 + aoff, q2 + aoff, qlast + aoff };
    const float* Wseg[3] = { Wq1, Wq2, Wql };
    int tid = threadIdx.x, lane = tid & 31, wid = tid >> 5;
    int wm0 = (wid >> 2) * 64, wn0 = (wid & 3) * 32;
    float acc[4][4][4] = {};
#pragma unroll
    for (int i = 0; i < 2; i++) {
        int idx = tid + i * 256;
        int m = idx >> 2, c4 = (idx & 3) * 4;
        float4 v = *(const float4*)(Aseg[0] + (size_t)m * E_ + c4);
        As[0][c4][m] = v.x; As[0][c4 + 1][m] = v.y; As[0][c4 + 2][m] = v.z; As[0][c4 + 3][m] = v.w;
        int k = idx >> 5, n4 = (idx & 31) * 4;
        *(float4*)&Bs[0][k][n4] = *(const float4*)(Wseg[0] + (size_t)k * HQ_ + n4);
    }
    __syncthreads();
    int buf = 0;
    for (int kt = 0; kt < 384; kt += BK) {
        float4 pa[2], pb[2];
        bool nx = (kt + BK) < 384;
        if (nx) {
            int ktn = kt + BK, seg = ktn >> 7, kl = ktn & 127;
            const float* A = Aseg[seg];
            const float* W = Wseg[seg];
#pragma unroll
            for (int i = 0; i < 2; i++) {
                int idx = tid + i * 256;
                int m = idx >> 2, c4 = (idx & 3) * 4;
                pa[i] = *(const float4*)(A + (size_t)m * E_ + kl + c4);
                int k = idx >> 5, n4 = (idx & 31) * 4;
                pb[i] = *(const float4*)(W + (size_t)(kl + k) * HQ_ + n4);
            }
        }
        wtile(acc, As[buf], Bs[buf], wm0, wn0, lane);
        if (nx) {
#pragma unroll
            for (int i = 0; i < 2; i++) {
                int idx = tid + i * 256;
                int m = idx >> 2, c4 = (idx & 3) * 4;
                As[buf ^ 1][c4][m] = pa[i].x; As[buf ^ 1][c4 + 1][m] = pa[i].y;
                As[buf ^ 1][c4 + 2][m] = pa[i].z; As[buf ^ 1][c4 + 3][m] = pa[i].w;
                int k = idx >> 5, n4 = (idx & 31) * 4;
                *(float4*)&Bs[buf ^ 1][k][n4] = pb[i];
            }
        }
        __syncthreads();
        buf ^= 1;
    }
    int gr = lane >> 2, gc = (lane & 3) * 2;
    size_t bp0 = (size_t)b * P_ + (size_t)mt * BM;
#pragma unroll
    for (int t = 0; t < 4; t++) {
        int r = wm0 + t * 16 + gr;
        float ldA = loadv[bp0 + r],     lfA = leftv[bp0 + r];
        float ldB = loadv[bp0 + r + 8], lfB = leftv[bp0 + r + 8];
#pragma unroll
        for (int u = 0; u < 4; u++) {
            int c = wn0 + u * 8 + gc;
            float2 w1 = *(const float2*)&Wql[128 * HQ_ + c];
            float2 w2 = *(const float2*)&Wql[129 * HQ_ + c];
            float q0  = acc[t][u][0] + ldA * w1.x + lfA * w2.x;
            float q1v = acc[t][u][1] + ldA * w1.y + lfA * w2.y;
            float q2v = acc[t][u][2] + ldB * w1.x + lfB * w2.x;
            float q3  = acc[t][u][3] + ldB * w1.y + lfB * w2.y;
            *(float2*)&g_sq[(bp0 + r) * (size_t)HQ_ + c] =
                make_float2(1.f / (1.f + __expf(-q0)), 1.f / (1.f + __expf(-q1v)));
            *(float2*)&g_sq[(bp0 + r + 8) * (size_t)HQ_ + c] =
                make_float2(1.f / (1.f + __expf(-q2v)), 1.f / (1.f + __expf(-q3)));
        }
    }
}

// ---------------- K3: [den|num] = exp(ninf - c*cur) @ [ek|ekv] ----------------
__global__ __launch_bounds__(256) void k3_aft(const float* __restrict__ cur,
                                              const float* __restrict__ ninf,
                                              const float* __restrict__ lsp,
                                              const float* __restrict__ alp) {
    __shared__ float As[2][BK][SPW], Bs[2][BK][SPW];
    int b = blockIdx.z, mt = blockIdx.y, ct = blockIdx.x;
    const float* A  = cur  + ((size_t)b * P_ + (size_t)mt * BM) * N_;
    const float* Nf = ninf + ((size_t)b * P_ + (size_t)mt * BM) * N_;
    const float* Bg = g_ekv + (size_t)b * N_ * 256 + ct * 128;
    float* C = g_nd + ((size_t)b * P_ + (size_t)mt * BM) * 256 + ct * 128;
    float cmul = lsp[0] * alp[0];
    int tid = threadIdx.x, lane = tid & 31, wid = tid >> 5;
    int wm0 = (wid >> 2) * 64, wn0 = (wid & 3) * 32;
    float acc[4][4][4] = {};
#pragma unroll
    for (int i = 0; i < 2; i++) {
        int idx = tid + i * 256;
        int m = idx >> 2, c4 = (idx & 3) * 4;
        float4 x = *(const float4*)(A  + (size_t)m * N_ + c4);
        float4 f = *(const float4*)(Nf + (size_t)m * N_ + c4);
        As[0][c4][m]     = __expf(f.x - cmul * x.x);
        As[0][c4 + 1][m] = __expf(f.y - cmul * x.y);
        As[0][c4 + 2][m] = __expf(f.z - cmul * x.z);
        As[0][c4 + 3][m] = __expf(f.w - cmul * x.w);
        int k = idx >> 5, n4 = (idx & 31) * 4;
        *(float4*)&Bs[0][k][n4] = *(const float4*)(Bg + (size_t)k * 256 + n4);
    }
    __syncthreads();
    int buf = 0;
    for (int kt = 0; kt < N_; kt += BK) {
        float4 px[2], pf[2], pb[2];
        bool nx = (kt + BK) < N_;
        if (nx) {
#pragma unroll
            for (int i = 0; i < 2; i++) {
                int idx = tid + i * 256;
                int m = idx >> 2, c4 = (idx & 3) * 4;
                px[i] = *(const float4*)(A  + (size_t)m * N_ + kt + BK + c4);
                pf[i] = *(const float4*)(Nf + (size_t)m * N_ + kt + BK + c4);
                int k = idx >> 5, n4 = (idx & 31) * 4;
                pb[i] = *(const float4*)(Bg + (size_t)(kt + BK + k) * 256 + n4);
            }
        }
        wtile(acc, As[buf], Bs[buf], wm0, wn0, lane);
        if (nx) {
#pragma unroll
            for (int i = 0; i < 2; i++) {
                int idx = tid + i * 256;
                int m = idx >> 2, c4 = (idx & 3) * 4;
                As[buf ^ 1][c4][m]     = __expf(pf[i].x - cmul * px[i].x);
                As[buf ^ 1][c4 + 1][m] = __expf(pf[i].y - cmul * px[i].y);
                As[buf ^ 1][c4 + 2][m] = __expf(pf[i].z - cmul * px[i].z);
                As[buf ^ 1][c4 + 3][m] = __expf(pf[i].w - cmul * px[i].w);
                int k = idx >> 5, n4 = (idx & 31) * 4;
                *(float4*)&Bs[buf ^ 1][k][n4] = pb[i];
            }
        }
        __syncthreads();
        buf ^= 1;
    }
    int gr = lane >> 2, gc = (lane & 3) * 2;
#pragma unroll
    for (int t = 0; t < 4; t++)
#pragma unroll
        for (int u = 0; u < 4; u++) {
            int r = wm0 + t * 16 + gr, c = wn0 + u * 8 + gc;
            *(float2*)&C[(size_t)r * 256 + c]       = make_float2(acc[t][u][0], acc[t][u][1]);
            *(float2*)&C[(size_t)(r + 8) * 256 + c] = make_float2(acc[t][u][2], acc[t][u][3]);
        }
}

// ---------------- K3b: AFT_out ----------------
__global__ void k3b_aft() {
    size_t i = (size_t)blockIdx.x * blockDim.x + threadIdx.x;
    size_t bp = i >> 7; int d = (int)(i & 127);
    float den = g_nd[bp * 256 + d];
    float num = g_nd[bp * 256 + 128 + d];
    g_aft[i] = g_sq[i] * num / (den + 1e-20f);
}

// ---------------- K4: score GEMM + tanh/exp + partial row sums ----------------
__global__ __launch_bounds__(256) void k4_score(const float* __restrict__ enc,
                                                const float* __restrict__ cur,
                                                const float* __restrict__ ninf,
                                                const float* __restrict__ lsp,
                                                const float* __restrict__ palp,
                                                float* __restrict__ out) {
    __shared__ float As[2][BK][SPW], Bs[2][BK][SPW];
    __shared__ float rs[BM];
    int b = blockIdx.z, mt = blockIdx.y, nt = blockIdx.x;
    const float* A  = g_aft + ((size_t)b * P_ + (size_t)mt * BM) * HQ_;
    const float* Bn = enc   + ((size_t)b * N_ + (size_t)nt * BN) * E_;
    float pc = lsp[0] * palp[0];
    int tid = threadIdx.x, lane = tid & 31, wid = tid >> 5;
    int wm0 = (wid >> 2) * 64, wn0 = (wid & 3) * 32;
    if (tid < BM) rs[tid] = 0.f;
    float acc[4][4][4] = {};
#pragma unroll
    for (int i = 0; i < 2; i++) {
        int idx = tid + i * 256;
        int m = idx >> 2, c4 = (idx & 3) * 4;
        float4 v = *(const float4*)(A + (size_t)m * HQ_ + c4);
        As[0][c4][m] = v.x; As[0][c4 + 1][m] = v.y; As[0][c4 + 2][m] = v.z; As[0][c4 + 3][m] = v.w;
        float4 w = *(const float4*)(Bn + (size_t)m * E_ + c4);
        Bs[0][c4][m] = w.x; Bs[0][c4 + 1][m] = w.y; Bs[0][c4 + 2][m] = w.z; Bs[0][c4 + 3][m] = w.w;
    }
    __syncthreads();
    int buf = 0;
    for (int kt = 0; kt < E_; kt += BK) {
        float4 pa[2], pb[2];
        bool nx = (kt + BK) < E_;
        if (nx) {
#pragma unroll
            for (int i = 0; i < 2; i++) {
                int idx = tid + i * 256;
                int m = idx >> 2, c4 = (idx & 3) * 4;
                pa[i] = *(const float4*)(A  + (size_t)m * HQ_ + kt + BK + c4);
                pb[i] = *(const float4*)(Bn + (size_t)m * E_  + kt + BK + c4);
            }
        }
        wtile(acc, As[buf], Bs[buf], wm0, wn0, lane);
        if (nx) {
#pragma unroll
            for (int i = 0; i < 2; i++) {
                int idx = tid + i * 256;
                int m = idx >> 2, c4 = (idx & 3) * 4;
                As[buf ^ 1][c4][m] = pa[i].x; As[buf ^ 1][c4 + 1][m] = pa[i].y;
                As[buf ^ 1][c4 + 2][m] = pa[i].z; As[buf ^ 1][c4 + 3][m] = pa[i].w;
                Bs[buf ^ 1][c4][m] = pb[i].x; Bs[buf ^ 1][c4 + 1][m] = pb[i].y;
                Bs[buf ^ 1][c4 + 2][m] = pb[i].z; Bs[buf ^ 1][c4 + 3][m] = pb[i].w;
            }
        }
        __syncthreads();
        buf ^= 1;
    }
    int gr = lane >> 2, gc = (lane & 3) * 2;
    size_t base = (size_t)b * P_ * N_;
#pragma unroll
    for (int t = 0; t < 4; t++) {
        float rsum0 = 0.f, rsum1 = 0.f;
        int p0 = mt * BM + wm0 + t * 16 + gr;
#pragma unroll
        for (int u = 0; u < 4; u++) {
            int n = nt * BN + wn0 + u * 8 + gc;
            size_t i0 = base + (size_t)p0 * N_ + n;
            size_t i1 = base + (size_t)(p0 + 8) * N_ + n;
            float2 cd0 = *(const float2*)&cur[i0];
            float2 nf0 = *(const float2*)&ninf[i0];
            float2 cd1 = *(const float2*)&cur[i1];
            float2 nf1 = *(const float2*)&ninf[i1];
            float s0 = acc[t][u][0] * (1.0f / SQRT_E_F) - pc * cd0.x;
            float s1 = acc[t][u][1] * (1.0f / SQRT_E_F) - pc * cd0.y;
            float s2 = acc[t][u][2] * (1.0f / SQRT_E_F) - pc * cd1.x;
            float s3 = acc[t][u][3] * (1.0f / SQRT_E_F) - pc * cd1.y;
            float u0 = __expf(10.0f * tanhf(s0) + nf0.x);
            float u1 = __expf(10.0f * tanhf(s1) + nf0.y);
            float u2 = __expf(10.0f * tanhf(s2) + nf1.x);
            float u3 = __expf(10.0f * tanhf(s3) + nf1.y);
            *(float2*)&out[i0] = make_float2(u0, u1);
            *(float2*)&out[i1] = make_float2(u2, u3);
            rsum0 += u0 + u1;
            rsum1 += u2 + u3;
        }
        atomicAdd(&rs[wm0 + t * 16 + gr], rsum0);
        atomicAdd(&rs[wm0 + t * 16 + gr + 8], rsum1);
    }
    __syncthreads();
    if (tid < BM) atomicAdd(&g_rowsum[(size_t)b * P_ + mt * BM + tid], rs[tid]);
}

// ---------------- K4b: normalize ----------------
__global__ void k4b_norm(float* __restrict__ out) {
    size_t i4 = ((size_t)blockIdx.x * blockDim.x + threadIdx.x) * 4;
    size_t row = i4 >> 10;
    float inv = 1.0f / g_rowsum[row];
    float4 v = *(float4*)(out + i4);
    v.x *= inv; v.y *= inv; v.z *= inv; v.w *= inv;
    *(float4*)(out + i4) = v;
}

// ---------------- launch ----------------
extern "C" void kernel_launch(void* const* d_in, const int* in_sizes, int n_in,
                              void* d_out, int out_size) {
    const float* enc   = (const float*)d_in[0];
    const float* q1    = (const float*)d_in[1];
    const float* q2    = (const float*)d_in[2];
    const float* qlast = (const float*)d_in[3];
    const float* loadv = (const float*)d_in[4];
    const float* leftv = (const float*)d_in[5];
    const float* cur   = (const float*)d_in[6];
    const float* lsp   = (const float*)d_in[7];
    const float* ninf  = (const float*)d_in[8];
    const float* Wq1   = (const float*)d_in[9];
    const float* Wq2   = (const float*)d_in[10];
    const float* Wql   = (const float*)d_in[11];
    const float* Wk    = (const float*)d_in[12];
    const float* Wv    = (const float*)d_in[13];
    const float* aalp  = (const float*)d_in[14];
    const float* palp  = (const float*)d_in[15];
    float* out = (float*)d_out;

    zero_rowsum_k<<<(B_ * P_ + 255) / 256, 256>>>();
    k1_kv<<<dim3(2, N_ / BM, B_), 256>>>(enc, Wk, Wv);
    k1b_expkv<<<(B_ * N_ * 128) / 256, 256>>>();
    k2_q<<<dim3(1, P_ / BM, B_), 256>>>(q1, q2, qlast, Wq1, Wq2, Wql, loadv, leftv);
    k3_aft<<<dim3(2, P_ / BM, B_), 256>>>(cur, ninf, lsp, aalp);
    k3b_aft<<<(B_ * P_ * 128) / 256, 256>>>();
    k4_score<<<dim3(N_ / BN, P_ / BM, B_), 256>>>(enc, cur, ninf, lsp, palp, out);
    k4b_norm<<<(B_ * (size_t)P_ * N_ / 4) / 256, 256>>>(out);
}

// round 5
// speedup vs baseline: 2.3819x; 1.6589x over previous
#include <cuda_runtime.h>
#include <math.h>

#define B_  32
#define P_  1024
#define N_  1024
#define E_  128
#define HQ_ 128
#define SQRT_E_F 11.313708498984761f

#define BM 128
#define BN 128
#define BK 16
#define ASTR 24    // A plane row stride in halves (16 used, 48B rows -> conflict-free ldmatrix)
#define BSTR 152   // B k-major plane row stride in halves (128 used, 304B rows)
#define ABUF (BM * ASTR * 2)   // 6144 B per A-plane buffer
#define BBUF (BK * BSTR * 2)   // 4864 B per B-plane buffer

// ---------------- scratch ----------------
__device__ float g_ekv[(size_t)B_ * N_ * 256];   // [b][n][0:128]=ek, [128:256]=ek*v
__device__ float g_sq [(size_t)B_ * P_ * HQ_];   // sigmoid(q)
__device__ float g_nd [(size_t)B_ * P_ * 256];   // [0:128]=den, [128:256]=num
__device__ float g_aft[(size_t)B_ * P_ * HQ_];   // AFT_out
__device__ float g_rowsum[B_ * P_];

// ---------------- bf16x2 split helpers ----------------
__device__ __forceinline__ unsigned packbf(float lo, float hi) {
    unsigned r; asm("cvt.rn.bf16x2.f32 %0, %1, %2;" : "=r"(r) : "f"(hi), "f"(lo)); return r;
}
__device__ __forceinline__ void split2(float x0, float x1, unsigned &h, unsigned &l) {
    h = packbf(x0, x1);
    float h0 = __uint_as_float(h << 16);
    float h1 = __uint_as_float(h & 0xFFFF0000u);
    l = packbf(x0 - h0, x1 - h1);
}
__device__ __forceinline__ void mma16(float* d, const unsigned* a, const unsigned* b) {
    asm("mma.sync.aligned.m16n8k16.row.col.f32.bf16.bf16.f32 "
        "{%0,%1,%2,%3},{%4,%5,%6,%7},{%8,%9},{%0,%1,%2,%3};"
        : "+f"(d[0]), "+f"(d[1]), "+f"(d[2]), "+f"(d[3])
        : "r"(a[0]), "r"(a[1]), "r"(a[2]), "r"(a[3]), "r"(b[0]), "r"(b[1]));
}
__device__ __forceinline__ void ldm4(unsigned* r, unsigned addr) {
    asm volatile("ldmatrix.sync.aligned.m8n8.x4.shared.b16 {%0,%1,%2,%3}, [%4];"
                 : "=r"(r[0]), "=r"(r[1]), "=r"(r[2]), "=r"(r[3]) : "r"(addr));
}
__device__ __forceinline__ void ldm4t(unsigned* r, unsigned addr) {
    asm volatile("ldmatrix.sync.aligned.m8n8.x4.trans.shared.b16 {%0,%1,%2,%3}, [%4];"
                 : "=r"(r[0]), "=r"(r[1]), "=r"(r[2]), "=r"(r[3]) : "r"(addr));
}

// warp tile: 64x32 of the 128x128 block; 12 ldmatrix + 48 mma per BK=16 chunk
template<int BSTEP, bool TRANS>
__device__ __forceinline__ void wtile(float acc[4][4][4],
        unsigned aAh, unsigned aAl, unsigned aBh, unsigned aBl) {
    unsigned bfh[2][4], bfl[2][4];
    if (TRANS) {
        ldm4t(bfh[0], aBh); ldm4t(bfh[1], aBh + BSTEP);
        ldm4t(bfl[0], aBl); ldm4t(bfl[1], aBl + BSTEP);
    } else {
        ldm4(bfh[0], aBh); ldm4(bfh[1], aBh + BSTEP);
        ldm4(bfl[0], aBl); ldm4(bfl[1], aBl + BSTEP);
    }
#pragma unroll
    for (int t = 0; t < 4; t++) {
        unsigned ah[4], al[4];
        ldm4(ah, aAh + t * 768);
        ldm4(al, aAl + t * 768);
#pragma unroll
        for (int u = 0; u < 4; u++) {
            const unsigned* bh = &bfh[u >> 1][(u & 1) * 2];
            const unsigned* bl = &bfl[u >> 1][(u & 1) * 2];
            mma16(acc[t][u], ah, bh);
            mma16(acc[t][u], al, bh);
            mma16(acc[t][u], ah, bl);
        }
    }
}

// ---------------- utility ----------------
__global__ void zero_rowsum_k() {
    int i = blockIdx.x * blockDim.x + threadIdx.x;
    if (i < B_ * P_) g_rowsum[i] = 0.f;
}

// ---------------- K1: k = enc@Wk, v = enc@Wv ----------------
__global__ __launch_bounds__(256) void k1_kv(const float* __restrict__ enc,
                                             const float* __restrict__ Wk,
                                             const float* __restrict__ Wv) {
    __shared__ unsigned short sAh[2][BM][ASTR], sAl[2][BM][ASTR];
    __shared__ unsigned short sBh[2][BK][BSTR], sBl[2][BK][BSTR];
    int b = blockIdx.z, mt = blockIdx.y, ct = blockIdx.x;
    const float* A = enc + ((size_t)b * N_ + (size_t)mt * BM) * E_;
    const float* W = ct ? Wv : Wk;
    float* C = g_ekv + ((size_t)b * N_ + (size_t)mt * BM) * 256 + ct * 128;
    int tid = threadIdx.x, lane = tid & 31, wid = tid >> 5;
    int wm0 = (wid >> 2) * 64, wn0 = (wid & 3) * 32;
    int q = lane >> 3, rr = lane & 7;
    unsigned bAh = (unsigned)__cvta_generic_to_shared(sAh);
    unsigned bAl = (unsigned)__cvta_generic_to_shared(sAl);
    unsigned bBh = (unsigned)__cvta_generic_to_shared(sBh);
    unsigned bBl = (unsigned)__cvta_generic_to_shared(sBl);
    unsigned aoff = (unsigned)((wm0 + (q & 1) * 8 + rr) * 48 + (q >> 1) * 16);
    unsigned boff = (unsigned)(((q & 1) * 8 + rr) * 304 + (q >> 1) * 16 + wn0 * 2);
    float acc[4][4][4] = {};
#pragma unroll
    for (int i = 0; i < 2; i++) {
        int idx = tid + i * 256;
        int m = idx >> 2, c4 = (idx & 3) * 4;
        float4 v = *(const float4*)(A + (size_t)m * E_ + c4);
        unsigned h0, l0, h1, l1;
        split2(v.x, v.y, h0, l0); split2(v.z, v.w, h1, l1);
        *(unsigned*)&sAh[0][m][c4] = h0; *(unsigned*)&sAh[0][m][c4 + 2] = h1;
        *(unsigned*)&sAl[0][m][c4] = l0; *(unsigned*)&sAl[0][m][c4 + 2] = l1;
        int k = idx >> 5, n0 = (idx & 31) * 4;
        float4 w = *(const float4*)(W + (size_t)k * HQ_ + n0);
        split2(w.x, w.y, h0, l0); split2(w.z, w.w, h1, l1);
        *(unsigned*)&sBh[0][k][n0] = h0; *(unsigned*)&sBh[0][k][n0 + 2] = h1;
        *(unsigned*)&sBl[0][k][n0] = l0; *(unsigned*)&sBl[0][k][n0 + 2] = l1;
    }
    __syncthreads();
    int buf = 0;
    for (int kt = 0; kt < E_; kt += BK) {
        float4 pa[2], pb[2];
        bool nx = (kt + BK) < E_;
        if (nx) {
#pragma unroll
            for (int i = 0; i < 2; i++) {
                int idx = tid + i * 256;
                int m = idx >> 2, c4 = (idx & 3) * 4;
                pa[i] = *(const float4*)(A + (size_t)m * E_ + kt + BK + c4);
                int k = idx >> 5, n0 = (idx & 31) * 4;
                pb[i] = *(const float4*)(W + (size_t)(kt + BK + k) * HQ_ + n0);
            }
        }
        wtile<32, true>(acc, bAh + buf * ABUF + aoff, bAl + buf * ABUF + aoff,
                        bBh + buf * BBUF + boff, bBl + buf * BBUF + boff);
        if (nx) {
            int nb = buf ^ 1;
#pragma unroll
            for (int i = 0; i < 2; i++) {
                int idx = tid + i * 256;
                int m = idx >> 2, c4 = (idx & 3) * 4;
                unsigned h0, l0, h1, l1;
                split2(pa[i].x, pa[i].y, h0, l0); split2(pa[i].z, pa[i].w, h1, l1);
                *(unsigned*)&sAh[nb][m][c4] = h0; *(unsigned*)&sAh[nb][m][c4 + 2] = h1;
                *(unsigned*)&sAl[nb][m][c4] = l0; *(unsigned*)&sAl[nb][m][c4 + 2] = l1;
                int k = idx >> 5, n0 = (idx & 31) * 4;
                split2(pb[i].x, pb[i].y, h0, l0); split2(pb[i].z, pb[i].w, h1, l1);
                *(unsigned*)&sBh[nb][k][n0] = h0; *(unsigned*)&sBh[nb][k][n0 + 2] = h1;
                *(unsigned*)&sBl[nb][k][n0] = l0; *(unsigned*)&sBl[nb][k][n0 + 2] = l1;
            }
        }
        __syncthreads();
        buf ^= 1;
    }
    int gr = lane >> 2, gc = (lane & 3) * 2;
#pragma unroll
    for (int t = 0; t < 4; t++)
#pragma unroll
        for (int u = 0; u < 4; u++) {
            int r = wm0 + t * 16 + gr, c = wn0 + u * 8 + gc;
            *(float2*)&C[(size_t)r * 256 + c]       = make_float2(acc[t][u][0], acc[t][u][1]);
            *(float2*)&C[(size_t)(r + 8) * 256 + c] = make_float2(acc[t][u][2], acc[t][u][3]);
        }
}

// ---------------- K1b: ek = exp(k), ekv = ek*v ----------------
__global__ void k1b_expkv() {
    size_t i = (size_t)blockIdx.x * blockDim.x + threadIdx.x;
    size_t bn = i >> 7; int d = (int)(i & 127);
    float k = g_ekv[bn * 256 + d];
    float v = g_ekv[bn * 256 + 128 + d];
    float ek = __expf(k);
    g_ekv[bn * 256 + d]       = ek;
    g_ekv[bn * 256 + 128 + d] = ek * v;
}

// ---------------- K2: q projections + sigmoid ----------------
__global__ __launch_bounds__(256) void k2_q(const float* __restrict__ q1,
                                            const float* __restrict__ q2,
                                            const float* __restrict__ qlast,
                                            const float* __restrict__ Wq1,
                                            const float* __restrict__ Wq2,
                                            const float* __restrict__ Wql,
                                            const float* __restrict__ loadv,
                                            const float* __restrict__ leftv) {
    __shared__ unsigned short sAh[2][BM][ASTR], sAl[2][BM][ASTR];
    __shared__ unsigned short sBh[2][BK][BSTR], sBl[2][BK][BSTR];
    int b = blockIdx.z, mt = blockIdx.y;
    size_t aoffm = ((size_t)b * P_ + (size_t)mt * BM) * E_;
    const float* Aseg[3] = { q1 + aoffm, q2 + aoffm, qlast + aoffm };
    const float* Wseg[3] = { Wq1, Wq2, Wql };
    int tid = threadIdx.x, lane = tid & 31, wid = tid >> 5;
    int wm0 = (wid >> 2) * 64, wn0 = (wid & 3) * 32;
    int q = lane >> 3, rr = lane & 7;
    unsigned bAh = (unsigned)__cvta_generic_to_shared(sAh);
    unsigned bAl = (unsigned)__cvta_generic_to_shared(sAl);
    unsigned bBh = (unsigned)__cvta_generic_to_shared(sBh);
    unsigned bBl = (unsigned)__cvta_generic_to_shared(sBl);
    unsigned aoff = (unsigned)((wm0 + (q & 1) * 8 + rr) * 48 + (q >> 1) * 16);
    unsigned boff = (unsigned)(((q & 1) * 8 + rr) * 304 + (q >> 1) * 16 + wn0 * 2);
    float acc[4][4][4] = {};
#pragma unroll
    for (int i = 0; i < 2; i++) {
        int idx = tid + i * 256;
        int m = idx >> 2, c4 = (idx & 3) * 4;
        float4 v = *(const float4*)(Aseg[0] + (size_t)m * E_ + c4);
        unsigned h0, l0, h1, l1;
        split2(v.x, v.y, h0, l0); split2(v.z, v.w, h1, l1);
        *(unsigned*)&sAh[0][m][c4] = h0; *(unsigned*)&sAh[0][m][c4 + 2] = h1;
        *(unsigned*)&sAl[0][m][c4] = l0; *(unsigned*)&sAl[0][m][c4 + 2] = l1;
        int k = idx >> 5, n0 = (idx & 31) * 4;
        float4 w = *(const float4*)(Wseg[0] + (size_t)k * HQ_ + n0);
        split2(w.x, w.y, h0, l0); split2(w.z, w.w, h1, l1);
        *(unsigned*)&sBh[0][k][n0] = h0; *(unsigned*)&sBh[0][k][n0 + 2] = h1;
        *(unsigned*)&sBl[0][k][n0] = l0; *(unsigned*)&sBl[0][k][n0 + 2] = l1;
    }
    __syncthreads();
    int buf = 0;
    for (int kt = 0; kt < 384; kt += BK) {
        float4 pa[2], pb[2];
        bool nx = (kt + BK) < 384;
        if (nx) {
            int ktn = kt + BK, seg = ktn >> 7, kl = ktn & 127;
            const float* A = Aseg[seg];
            const float* W = Wseg[seg];
#pragma unroll
            for (int i = 0; i < 2; i++) {
                int idx = tid + i * 256;
                int m = idx >> 2, c4 = (idx & 3) * 4;
                pa[i] = *(const float4*)(A + (size_t)m * E_ + kl + c4);
                int k = idx >> 5, n0 = (idx & 31) * 4;
                pb[i] = *(const float4*)(W + (size_t)(kl + k) * HQ_ + n0);
            }
        }
        wtile<32, true>(acc, bAh + buf * ABUF + aoff, bAl + buf * ABUF + aoff,
                        bBh + buf * BBUF + boff, bBl + buf * BBUF + boff);
        if (nx) {
            int nb = buf ^ 1;
#pragma unroll
            for (int i = 0; i < 2; i++) {
                int idx = tid + i * 256;
                int m = idx >> 2, c4 = (idx & 3) * 4;
                unsigned h0, l0, h1, l1;
                split2(pa[i].x, pa[i].y, h0, l0); split2(pa[i].z, pa[i].w, h1, l1);
                *(unsigned*)&sAh[nb][m][c4] = h0; *(unsigned*)&sAh[nb][m][c4 + 2] = h1;
                *(unsigned*)&sAl[nb][m][c4] = l0; *(unsigned*)&sAl[nb][m][c4 + 2] = l1;
                int k = idx >> 5, n0 = (idx & 31) * 4;
                split2(pb[i].x, pb[i].y, h0, l0); split2(pb[i].z, pb[i].w, h1, l1);
                *(unsigned*)&sBh[nb][k][n0] = h0; *(unsigned*)&sBh[nb][k][n0 + 2] = h1;
                *(unsigned*)&sBl[nb][k][n0] = l0; *(unsigned*)&sBl[nb][k][n0 + 2] = l1;
            }
        }
        __syncthreads();
        buf ^= 1;
    }
    int gr = lane >> 2, gc = (lane & 3) * 2;
    size_t bp0 = (size_t)b * P_ + (size_t)mt * BM;
#pragma unroll
    for (int t = 0; t < 4; t++) {
        int r = wm0 + t * 16 + gr;
        float ldA = loadv[bp0 + r],     lfA = leftv[bp0 + r];
        float ldB = loadv[bp0 + r + 8], lfB = leftv[bp0 + r + 8];
#pragma unroll
        for (int u = 0; u < 4; u++) {
            int c = wn0 + u * 8 + gc;
            float2 w1 = *(const float2*)&Wql[128 * HQ_ + c];
            float2 w2 = *(const float2*)&Wql[129 * HQ_ + c];
            float q0  = acc[t][u][0] + ldA * w1.x + lfA * w2.x;
            float q1v = acc[t][u][1] + ldA * w1.y + lfA * w2.y;
            float q2v = acc[t][u][2] + ldB * w1.x + lfB * w2.x;
            float q3  = acc[t][u][3] + ldB * w1.y + lfB * w2.y;
            *(float2*)&g_sq[(bp0 + r) * (size_t)HQ_ + c] =
                make_float2(1.f / (1.f + __expf(-q0)), 1.f / (1.f + __expf(-q1v)));
            *(float2*)&g_sq[(bp0 + r + 8) * (size_t)HQ_ + c] =
                make_float2(1.f / (1.f + __expf(-q2v)), 1.f / (1.f + __expf(-q3)));
        }
    }
}

// ---------------- K3: [den|num] = exp(ninf - c*cur) @ [ek|ekv] ----------------
__global__ __launch_bounds__(256) void k3_aft(const float* __restrict__ cur,
                                              const float* __restrict__ ninf,
                                              const float* __restrict__ lsp,
                                              const float* __restrict__ alp) {
    __shared__ unsigned short sAh[2][BM][ASTR], sAl[2][BM][ASTR];
    __shared__ unsigned short sBh[2][BK][BSTR], sBl[2][BK][BSTR];
    int b = blockIdx.z, mt = blockIdx.y, ct = blockIdx.x;
    const float* A  = cur  + ((size_t)b * P_ + (size_t)mt * BM) * N_;
    const float* Nf = ninf + ((size_t)b * P_ + (size_t)mt * BM) * N_;
    const float* Bg = g_ekv + (size_t)b * N_ * 256 + ct * 128;
    float* C = g_nd + ((size_t)b * P_ + (size_t)mt * BM) * 256 + ct * 128;
    float cmul = lsp[0] * alp[0];
    int tid = threadIdx.x, lane = tid & 31, wid = tid >> 5;
    int wm0 = (wid >> 2) * 64, wn0 = (wid & 3) * 32;
    int q = lane >> 3, rr = lane & 7;
    unsigned bAh = (unsigned)__cvta_generic_to_shared(sAh);
    unsigned bAl = (unsigned)__cvta_generic_to_shared(sAl);
    unsigned bBh = (unsigned)__cvta_generic_to_shared(sBh);
    unsigned bBl = (unsigned)__cvta_generic_to_shared(sBl);
    unsigned aoff = (unsigned)((wm0 + (q & 1) * 8 + rr) * 48 + (q >> 1) * 16);
    unsigned boff = (unsigned)(((q & 1) * 8 + rr) * 304 + (q >> 1) * 16 + wn0 * 2);
    float acc[4][4][4] = {};
#pragma unroll
    for (int i = 0; i < 2; i++) {
        int idx = tid + i * 256;
        int m = idx >> 2, c4 = (idx & 3) * 4;
        float4 x = *(const float4*)(A  + (size_t)m * N_ + c4);
        float4 f = *(const float4*)(Nf + (size_t)m * N_ + c4);
        float e0 = __expf(f.x - cmul * x.x), e1 = __expf(f.y - cmul * x.y);
        float e2 = __expf(f.z - cmul * x.z), e3 = __expf(f.w - cmul * x.w);
        unsigned h0, l0, h1, l1;
        split2(e0, e1, h0, l0); split2(e2, e3, h1, l1);
        *(unsigned*)&sAh[0][m][c4] = h0; *(unsigned*)&sAh[0][m][c4 + 2] = h1;
        *(unsigned*)&sAl[0][m][c4] = l0; *(unsigned*)&sAl[0][m][c4 + 2] = l1;
        int k = idx >> 5, n0 = (idx & 31) * 4;
        float4 w = *(const float4*)(Bg + (size_t)k * 256 + n0);
        split2(w.x, w.y, h0, l0); split2(w.z, w.w, h1, l1);
        *(unsigned*)&sBh[0][k][n0] = h0; *(unsigned*)&sBh[0][k][n0 + 2] = h1;
        *(unsigned*)&sBl[0][k][n0] = l0; *(unsigned*)&sBl[0][k][n0 + 2] = l1;
    }
    __syncthreads();
    int buf = 0;
    for (int kt = 0; kt < N_; kt += BK) {
        float4 px[2], pf[2], pb[2];
        bool nx = (kt + BK) < N_;
        if (nx) {
#pragma unroll
            for (int i = 0; i < 2; i++) {
                int idx = tid + i * 256;
                int m = idx >> 2, c4 = (idx & 3) * 4;
                px[i] = *(const float4*)(A  + (size_t)m * N_ + kt + BK + c4);
                pf[i] = *(const float4*)(Nf + (size_t)m * N_ + kt + BK + c4);
                int k = idx >> 5, n0 = (idx & 31) * 4;
                pb[i] = *(const float4*)(Bg + (size_t)(kt + BK + k) * 256 + n0);
            }
        }
        wtile<32, true>(acc, bAh + buf * ABUF + aoff, bAl + buf * ABUF + aoff,
                        bBh + buf * BBUF + boff, bBl + buf * BBUF + boff);
        if (nx) {
            int nb = buf ^ 1;
#pragma unroll
            for (int i = 0; i < 2; i++) {
                int idx = tid + i * 256;
                int m = idx >> 2, c4 = (idx & 3) * 4;
                float e0 = __expf(pf[i].x - cmul * px[i].x);
                float e1 = __expf(pf[i].y - cmul * px[i].y);
                float e2 = __expf(pf[i].z - cmul * px[i].z);
                float e3 = __expf(pf[i].w - cmul * px[i].w);
                unsigned h0, l0, h1, l1;
                split2(e0, e1, h0, l0); split2(e2, e3, h1, l1);
                *(unsigned*)&sAh[nb][m][c4] = h0; *(unsigned*)&sAh[nb][m][c4 + 2] = h1;
                *(unsigned*)&sAl[nb][m][c4] = l0; *(unsigned*)&sAl[nb][m][c4 + 2] = l1;
                int k = idx >> 5, n0 = (idx & 31) * 4;
                split2(pb[i].x, pb[i].y, h0, l0); split2(pb[i].z, pb[i].w, h1, l1);
                *(unsigned*)&sBh[nb][k][n0] = h0; *(unsigned*)&sBh[nb][k][n0 + 2] = h1;
                *(unsigned*)&sBl[nb][k][n0] = l0; *(unsigned*)&sBl[nb][k][n0 + 2] = l1;
            }
        }
        __syncthreads();
        buf ^= 1;
    }
    int gr = lane >> 2, gc = (lane & 3) * 2;
#pragma unroll
    for (int t = 0; t < 4; t++)
#pragma unroll
        for (int u = 0; u < 4; u++) {
            int r = wm0 + t * 16 + gr, c = wn0 + u * 8 + gc;
            *(float2*)&C[(size_t)r * 256 + c]       = make_float2(acc[t][u][0], acc[t][u][1]);
            *(float2*)&C[(size_t)(r + 8) * 256 + c] = make_float2(acc[t][u][2], acc[t][u][3]);
        }
}

// ---------------- K3b: AFT_out ----------------
__global__ void k3b_aft() {
    size_t i = (size_t)blockIdx.x * blockDim.x + threadIdx.x;
    size_t bp = i >> 7; int d = (int)(i & 127);
    float den = g_nd[bp * 256 + d];
    float num = g_nd[bp * 256 + 128 + d];
    g_aft[i] = g_sq[i] * num / (den + 1e-20f);
}

// ---------------- K4: score GEMM + tanh/exp + partial row sums ----------------
__global__ __launch_bounds__(256) void k4_score(const float* __restrict__ enc,
                                                const float* __restrict__ cur,
                                                const float* __restrict__ ninf,
                                                const float* __restrict__ lsp,
                                                const float* __restrict__ palp,
                                                float* __restrict__ out) {
    // B is [n][k] row-major (matches enc layout) -> non-trans ldmatrix B-frags
    __shared__ unsigned short sAh[2][BM][ASTR], sAl[2][BM][ASTR];
    __shared__ unsigned short sBh[2][BN][ASTR], sBl[2][BN][ASTR];
    int b = blockIdx.z, mt = blockIdx.y, nt = blockIdx.x;
    const float* A  = g_aft + ((size_t)b * P_ + (size_t)mt * BM) * HQ_;
    const float* Bn = enc   + ((size_t)b * N_ + (size_t)nt * BN) * E_;
    float pc = lsp[0] * palp[0];
    int tid = threadIdx.x, lane = tid & 31, wid = tid >> 5;
    int wm0 = (wid >> 2) * 64, wn0 = (wid & 3) * 32;
    int q = lane >> 3, rr = lane & 7;
    unsigned bAh = (unsigned)__cvta_generic_to_shared(sAh);
    unsigned bAl = (unsigned)__cvta_generic_to_shared(sAl);
    unsigned bBh = (unsigned)__cvta_generic_to_shared(sBh);
    unsigned bBl = (unsigned)__cvta_generic_to_shared(sBl);
    unsigned aoff = (unsigned)((wm0 + (q & 1) * 8 + rr) * 48 + (q >> 1) * 16);
    unsigned boff = (unsigned)((wn0 + (q >> 1) * 8 + rr) * 48 + (q & 1) * 16);
    float acc[4][4][4] = {};
#pragma unroll
    for (int i = 0; i < 2; i++) {
        int idx = tid + i * 256;
        int m = idx >> 2, c4 = (idx & 3) * 4;
        float4 v = *(const float4*)(A + (size_t)m * HQ_ + c4);
        unsigned h0, l0, h1, l1;
        split2(v.x, v.y, h0, l0); split2(v.z, v.w, h1, l1);
        *(unsigned*)&sAh[0][m][c4] = h0; *(unsigned*)&sAh[0][m][c4 + 2] = h1;
        *(unsigned*)&sAl[0][m][c4] = l0; *(unsigned*)&sAl[0][m][c4 + 2] = l1;
        float4 w = *(const float4*)(Bn + (size_t)m * E_ + c4);
        split2(w.x, w.y, h0, l0); split2(w.z, w.w, h1, l1);
        *(unsigned*)&sBh[0][m][c4] = h0; *(unsigned*)&sBh[0][m][c4 + 2] = h1;
        *(unsigned*)&sBl[0][m][c4] = l0; *(unsigned*)&sBl[0][m][c4 + 2] = l1;
    }
    __syncthreads();
    int buf = 0;
    for (int kt = 0; kt < E_; kt += BK) {
        float4 pa[2], pb[2];
        bool nx = (kt + BK) < E_;
        if (nx) {
#pragma unroll
            for (int i = 0; i < 2; i++) {
                int idx = tid + i * 256;
                int m = idx >> 2, c4 = (idx & 3) * 4;
                pa[i] = *(const float4*)(A  + (size_t)m * HQ_ + kt + BK + c4);
                pb[i] = *(const float4*)(Bn + (size_t)m * E_  + kt + BK + c4);
            }
        }
        wtile<768, false>(acc, bAh + buf * ABUF + aoff, bAl + buf * ABUF + aoff,
                          bBh + buf * ABUF + boff, bBl + buf * ABUF + boff);
        if (nx) {
            int nb = buf ^ 1;
#pragma unroll
            for (int i = 0; i < 2; i++) {
                int idx = tid + i * 256;
                int m = idx >> 2, c4 = (idx & 3) * 4;
                unsigned h0, l0, h1, l1;
                split2(pa[i].x, pa[i].y, h0, l0); split2(pa[i].z, pa[i].w, h1, l1);
                *(unsigned*)&sAh[nb][m][c4] = h0; *(unsigned*)&sAh[nb][m][c4 + 2] = h1;
                *(unsigned*)&sAl[nb][m][c4] = l0; *(unsigned*)&sAl[nb][m][c4 + 2] = l1;
                split2(pb[i].x, pb[i].y, h0, l0); split2(pb[i].z, pb[i].w, h1, l1);
                *(unsigned*)&sBh[nb][m][c4] = h0; *(unsigned*)&sBh[nb][m][c4 + 2] = h1;
                *(unsigned*)&sBl[nb][m][c4] = l0; *(unsigned*)&sBl[nb][m][c4 + 2] = l1;
            }
        }
        __syncthreads();
        buf ^= 1;
    }
    // reuse smem (all tiles consumed) for row-sum accumulation
    float* rs = (float*)sAh;
    if (tid < BM) rs[tid] = 0.f;
    __syncthreads();
    int gr = lane >> 2, gc = (lane & 3) * 2;
    size_t base = (size_t)b * P_ * N_;
#pragma unroll
    for (int t = 0; t < 4; t++) {
        float rsum0 = 0.f, rsum1 = 0.f;
        int p0 = mt * BM + wm0 + t * 16 + gr;
#pragma unroll
        for (int u = 0; u < 4; u++) {
            int n = nt * BN + wn0 + u * 8 + gc;
            size_t i0 = base + (size_t)p0 * N_ + n;
            size_t i1 = base + (size_t)(p0 + 8) * N_ + n;
            float2 cd0 = *(const float2*)&cur[i0];
            float2 nf0 = *(const float2*)&ninf[i0];
            float2 cd1 = *(const float2*)&cur[i1];
            float2 nf1 = *(const float2*)&ninf[i1];
            float s0 = acc[t][u][0] * (1.0f / SQRT_E_F) - pc * cd0.x;
            float s1 = acc[t][u][1] * (1.0f / SQRT_E_F) - pc * cd0.y;
            float s2 = acc[t][u][2] * (1.0f / SQRT_E_F) - pc * cd1.x;
            float s3 = acc[t][u][3] * (1.0f / SQRT_E_F) - pc * cd1.y;
            float u0 = __expf(10.0f * tanhf(s0) + nf0.x);
            float u1 = __expf(10.0f * tanhf(s1) + nf0.y);
            float u2 = __expf(10.0f * tanhf(s2) + nf1.x);
            float u3 = __expf(10.0f * tanhf(s3) + nf1.y);
            *(float2*)&out[i0] = make_float2(u0, u1);
            *(float2*)&out[i1] = make_float2(u2, u3);
            rsum0 += u0 + u1;
            rsum1 += u2 + u3;
        }
        atomicAdd(&rs[wm0 + t * 16 + gr], rsum0);
        atomicAdd(&rs[wm0 + t * 16 + gr + 8], rsum1);
    }
    __syncthreads();
    if (tid < BM) atomicAdd(&g_rowsum[(size_t)b * P_ + mt * BM + tid], rs[tid]);
}

// ---------------- K4b: normalize ----------------
__global__ void k4b_norm(float* __restrict__ out) {
    size_t i4 = ((size_t)blockIdx.x * blockDim.x + threadIdx.x) * 4;
    size_t row = i4 >> 10;
    float inv = 1.0f / g_rowsum[row];
    float4 v = *(float4*)(out + i4);
    v.x *= inv; v.y *= inv; v.z *= inv; v.w *= inv;
    *(float4*)(out + i4) = v;
}

// ---------------- launch ----------------
extern "C" void kernel_launch(void* const* d_in, const int* in_sizes, int n_in,
                              void* d_out, int out_size) {
    const float* enc   = (const float*)d_in[0];
    const float* q1    = (const float*)d_in[1];
    const float* q2    = (const float*)d_in[2];
    const float* qlast = (const float*)d_in[3];
    const float* loadv = (const float*)d_in[4];
    const float* leftv = (const float*)d_in[5];
    const float* cur   = (const float*)d_in[6];
    const float* lsp   = (const float*)d_in[7];
    const float* ninf  = (const float*)d_in[8];
    const float* Wq1   = (const float*)d_in[9];
    const float* Wq2   = (const float*)d_in[10];
    const float* Wql   = (const float*)d_in[11];
    const float* Wk    = (const float*)d_in[12];
    const float* Wv    = (const float*)d_in[13];
    const float* aalp  = (const float*)d_in[14];
    const float* palp  = (const float*)d_in[15];
    float* out = (float*)d_out;

    zero_rowsum_k<<<(B_ * P_ + 255) / 256, 256>>>();
    k1_kv<<<dim3(2, N_ / BM, B_), 256>>>(enc, Wk, Wv);
    k1b_expkv<<<(B_ * N_ * 128) / 256, 256>>>();
    k2_q<<<dim3(1, P_ / BM, B_), 256>>>(q1, q2, qlast, Wq1, Wq2, Wql, loadv, leftv);
    k3_aft<<<dim3(2, P_ / BM, B_), 256>>>(cur, ninf, lsp, aalp);
    k3b_aft<<<(B_ * P_ * 128) / 256, 256>>>();
    k4_score<<<dim3(N_ / BN, P_ / BM, B_), 256>>>(enc, cur, ninf, lsp, palp, out);
    k4b_norm<<<(B_ * (size_t)P_ * N_ / 4) / 256, 256>>>(out);
}